// round 15
// baseline (speedup 1.0000x reference)
#include <cuda_runtime.h>
#include <cuda_fp16.h>
#include <cstdint>
#include <cstddef>

#define N_PTS 32768
#define HID   256
#define KTEST 1024
#define PI_F  3.14159274101257324f

// ---------------- global scratch ----------------
// Fragment-major jets: [mt16(2048)][ch(3)][hl(2)][kt(16)][lane(32)] x uint4.
__device__ uint4 g_jetA[(size_t)2048 * 3 * 2 * 16 * 32];
__device__ uint4 g_jetB[(size_t)2048 * 3 * 2 * 16 * 32];
__device__ float g_part[(size_t)N_PTS * 16];
__device__ float g_r[N_PTS];
__device__ float g_Sp[8 * KTEST];
__device__ float g_ub[2];

// ---------------- math helpers ----------------
__device__ __forceinline__ float frcp(float x) {
    float r;
    asm("rcp.approx.f32 %0, %1;" : "=f"(r) : "f"(x));
    return r;
}

__device__ __forceinline__ void tanh4(const float* z, float* h) {
    float e[4], ep[4];
#pragma unroll
    for (int i = 0; i < 4; i++) {
        float zc = fminf(fmaxf(z[i], -9.0f), 9.0f);
        e[i]  = __expf(2.0f * zc);
        ep[i] = e[i] + 1.0f;
    }
    float p01   = ep[0] * ep[1];
    float p012  = p01 * ep[2];
    float p0123 = p012 * ep[3];
    float r = frcp(p0123);
    float i3 = p012 * r;  r *= ep[3];
    float i2 = p01  * r;  r *= ep[2];
    float i1 = ep[0] * r; r *= ep[1];
    float i0 = r;
    h[0] = (e[0] - 1.0f) * i0;
    h[1] = (e[1] - 1.0f) * i1;
    h[2] = (e[2] - 1.0f) * i2;
    h[3] = (e[3] - 1.0f) * i3;
}

__device__ __forceinline__ float my_sin(float a) {
    const float INV_PI = 0.3183098861837907f;
    float n = rintf(a * INV_PI);
    float r = fmaf(n, -3.14159274101257324f, a);
    r = fmaf(n, 8.742277657347586e-8f, r);
    float s2 = r * r;
    float p = -2.50521084e-8f;
    p = fmaf(p, s2, 2.75573192e-6f);
    p = fmaf(p, s2, -1.98412698e-4f);
    p = fmaf(p, s2, 8.33333333e-3f);
    p = fmaf(p, s2, -1.66666667e-1f);
    float s = fmaf(p * s2, r, r);
    return (((int)n) & 1) ? -s : s;
}

__device__ __forceinline__ void hsplit(float v, __half& hi, __half& lo) {
    hi = __float2half_rn(v);
    lo = __float2half_rn(v - __half2float(hi));
}

__device__ __forceinline__ uint32_t pack2(__half a, __half b) {
    __half2 t = __halves2half2(a, b);
    return *(uint32_t*)&t;
}

// fp16 HMMA (sm_80+ PTX).
__device__ __forceinline__ void mma16816(float* d, const uint32_t* a, const uint32_t* b) {
    asm volatile(
        "mma.sync.aligned.m16n8k16.row.col.f32.f16.f16.f32 "
        "{%0,%1,%2,%3}, {%4,%5,%6,%7}, {%8,%9}, {%0,%1,%2,%3};"
        : "+f"(d[0]), "+f"(d[1]), "+f"(d[2]), "+f"(d[3])
        : "r"(a[0]), "r"(a[1]), "r"(a[2]), "r"(a[3]), "r"(b[0]), "r"(b[1]));
}

// ldmatrix x4 (sm_75+ PTX).
__device__ __forceinline__ void ldsm4(uint32_t* r, uint32_t addr) {
    asm volatile("ldmatrix.sync.aligned.m8n8.x4.shared.b16 {%0,%1,%2,%3}, [%4];"
        : "=r"(r[0]), "=r"(r[1]), "=r"(r[2]), "=r"(r[3]) : "r"(addr));
}

__device__ __forceinline__ uint32_t smem_u32(const void* p) {
    uint32_t a;
    asm("{ .reg .u64 t; cvta.to.shared.u64 t, %1; cvt.u32.u64 %0, t; }" : "=r"(a) : "l"(p));
    return a;
}

// ---------------- SMEM geometry: B only (fp16 elements) ----------------
#define SB_E    136
#define BLO_E   8704                   // 64*136
#define SMEM_TOT (2 * 8704 * 2)        // 34816 B

#define NTHR 128

// jet index (in uint4 units)
__device__ __forceinline__ size_t jidx(int mt16, int ch, int hl, int kt, int lane) {
    return ((((size_t)mt16 * 3 + ch) * 2 + hl) * 16 + kt) * 32 + lane;
}

// Stage one K=128 half of B = W^T (fp16 hi/lo split), n tile = 64 cols. 128 thr.
__device__ __forceinline__ void stage_B(__half* sm, const float* __restrict__ W,
                                        int n0, int k0, int tid) {
#pragma unroll
    for (int it = 0; it < 16; it++) {
        int e = tid + it * NTHR;
        int k = e >> 4, n4 = e & 15;
        float4 v = *(const float4*)(W + (size_t)(k0 + k) * HID + n0 + n4 * 4);
        float vv[4] = {v.x, v.y, v.z, v.w};
#pragma unroll
        for (int u = 0; u < 4; u++) {
            __half hh, ll; hsplit(vv[u], hh, ll);
            int off = (n4 * 4 + u) * SB_E + k;
            sm[off]         = hh;
            sm[BLO_E + off] = ll;
        }
    }
}

// Load 12 A fragments: [mf(2)][ch(3)][hl(2)] for rows mt16b + mf.
__device__ __forceinline__ void load_A(uint4* dst, const uint4* __restrict__ jin,
                                       int mt16b, int kt, int lane) {
#pragma unroll
    for (int mf = 0; mf < 2; mf++)
#pragma unroll
        for (int ch = 0; ch < 3; ch++)
#pragma unroll
            for (int hl = 0; hl < 2; hl++)
                dst[(mf * 3 + ch) * 2 + hl] = __ldg(jin + jidx(mt16b + mf, ch, hl, kt, lane));
}

// ---------------- layer-0 jet init (fragment-major) ----------------
__global__ __launch_bounds__(256) void k_init(const float* __restrict__ x,
                                              const float* __restrict__ W0,
                                              const float* __restrict__ b0,
                                              uint4* __restrict__ jout) {
    int gid = blockIdx.x * 256 + threadIdx.x;
    int tile = gid >> 5, lane = gid & 31;
    int mt16 = tile >> 4, kt = tile & 15;
    int lg = lane >> 2, lq = lane & 3;

    float x0 = __ldg(x + mt16 * 16 + lg);
    float x1 = __ldg(x + mt16 * 16 + lg + 8);
    int kc[4] = {kt * 16 + 2 * lq, kt * 16 + 2 * lq + 1,
                 kt * 16 + 2 * lq + 8, kt * 16 + 2 * lq + 9};
    float w[4], b[4];
#pragma unroll
    for (int c = 0; c < 4; c++) { w[c] = __ldg(W0 + kc[c]); b[c] = __ldg(b0 + kc[c]); }

    float z[8], h[8];
#pragma unroll
    for (int c = 0; c < 4; c++) {
        z[c]     = fmaf(x0, w[c], b[c]);
        z[4 + c] = fmaf(x1, w[c], b[c]);
    }
    tanh4(z, h);
    tanh4(z + 4, h + 4);

    __half VH[3][8], VL[3][8];
#pragma unroll
    for (int e = 0; e < 8; e++) {
        int c = e & 3;
        float hv = h[e];
        float g  = fmaf(-hv, hv, 1.0f);
        float d  = g * w[c];
        float e2 = -2.0f * hv * g * w[c] * w[c];
        hsplit(hv, VH[0][e], VL[0][e]);
        hsplit(d,  VH[1][e], VL[1][e]);
        hsplit(e2, VH[2][e], VL[2][e]);
    }
#pragma unroll
    for (int ch = 0; ch < 3; ch++)
#pragma unroll
        for (int hl = 0; hl < 2; hl++) {
            const __half* A = hl ? VL[ch] : VH[ch];
            uint4 o;
            o.x = pack2(A[0], A[1]);
            o.y = pack2(A[4], A[5]);
            o.z = pack2(A[2], A[3]);
            o.w = pack2(A[6], A[7]);
            jout[jidx(mt16, ch, hl, kt, lane)] = o;
        }
}

// ---------------- fused hidden layer (CTA 64m x 64n, 4 warps, tile 32x32) ----------------
template<int WRITE_JET>
__global__ __launch_bounds__(NTHR, 2) void k_layer(
    const uint4* __restrict__ jin, uint4* __restrict__ jout,
    const float* __restrict__ W, const float* __restrict__ bias,
    const float* __restrict__ W3)
{
    extern __shared__ __half sm[];
    const int tid = threadIdx.x, lane = tid & 31, wid = tid >> 5;
    const int wm = wid & 1, wn = wid >> 1;
    const int lg = lane >> 2, lq = lane & 3;
    const int t  = lane >> 3, ri = lane & 7;
    const int nt = blockIdx.x & 3, mt = blockIdx.x >> 2;
    const int n0 = nt * 64;
    const int mt16b = mt * 4 + wm * 2;

    const uint32_t smb = smem_u32(sm);
    stage_B(sm, W, n0, 0, tid);

    float acc[3][2][4][4];
#pragma unroll
    for (int ch = 0; ch < 3; ch++)
#pragma unroll
        for (int mf = 0; mf < 2; mf++)
#pragma unroll
            for (int nf = 0; nf < 4; nf++)
#pragma unroll
                for (int rr = 0; rr < 4; rr++) acc[ch][mf][nf][rr] = 0.f;

    uint4 abuf[2][12];
    load_A(abuf[0], jin, mt16b, 0, lane);
    __syncthreads();   // B half 0 staged

    // ---- 16 k-tiles; per-warp A prefetch; only 2 barrier points (B restage) ----
#pragma unroll
    for (int kt = 0; kt < 16; kt++) {
        if (kt == 8) {
            __syncthreads();
            stage_B(sm, W, n0, 128, tid);
            __syncthreads();
        }
        if (kt < 15) load_A(abuf[(kt + 1) & 1], jin, mt16b, kt + 1, lane);

        const int kb = (kt & 7) * 16;
        uint32_t bh[4][2], bl[4][2];
#pragma unroll
        for (int nf = 0; nf < 4; nf++) {
            int n = wn * 32 + nf * 8 + ri;
            uint32_t el = ((t >> 1) ? BLO_E : 0) + n * SB_E + kb + (t & 1) * 8;
            uint32_t rg[4];
            ldsm4(rg, smb + el * 2);
            bh[nf][0] = rg[0]; bh[nf][1] = rg[1];
            bl[nf][0] = rg[2]; bl[nf][1] = rg[3];
        }
        const uint4* a = abuf[kt & 1];
#pragma unroll
        for (int ch = 0; ch < 3; ch++) {
#pragma unroll
            for (int mf = 0; mf < 2; mf++)
#pragma unroll
                for (int nf = 0; nf < 4; nf++)
                    mma16816(acc[ch][mf][nf],
                             (const uint32_t*)&a[(mf * 3 + ch) * 2 + 0], bh[nf]); // hi*hi
#pragma unroll
            for (int mf = 0; mf < 2; mf++)
#pragma unroll
                for (int nf = 0; nf < 4; nf++)
                    mma16816(acc[ch][mf][nf],
                             (const uint32_t*)&a[(mf * 3 + ch) * 2 + 0], bl[nf]); // hi*lo
#pragma unroll
            for (int mf = 0; mf < 2; mf++)
#pragma unroll
                for (int nf = 0; nf < 4; nf++)
                    mma16816(acc[ch][mf][nf],
                             (const uint32_t*)&a[(mf * 3 + ch) * 2 + 1], bh[nf]); // lo*hi
        }
    }

    // ---- epilogue (per mf) ----
#pragma unroll
    for (int mf = 0; mf < 2; mf++) {
        const int mt16 = mt16b + mf;
        float zz[16], aa[16], cc[16], hh[16];
#pragma unroll
        for (int rh = 0; rh < 2; rh++)
#pragma unroll
            for (int nf = 0; nf < 4; nf++)
#pragma unroll
                for (int u = 0; u < 2; u++) {
                    const int e = rh * 8 + nf * 2 + u;
                    const int col = n0 + wn * 32 + nf * 8 + lq * 2 + u;
                    zz[e] = acc[0][mf][nf][rh * 2 + u] + __ldg(bias + col);
                    aa[e] = acc[1][mf][nf][rh * 2 + u];
                    cc[e] = acc[2][mf][nf][rh * 2 + u];
                }
        tanh4(zz, hh); tanh4(zz + 4, hh + 4);
        tanh4(zz + 8, hh + 8); tanh4(zz + 12, hh + 12);

        if (WRITE_JET) {
            __half VH[3][16], VL[3][16];
#pragma unroll
            for (int e = 0; e < 16; e++) {
                float h = hh[e];
                float g = fmaf(-h, h, 1.0f);
                float d = g * aa[e];
                float ev = g * fmaf(-2.0f * h * aa[e], aa[e], cc[e]);
                hsplit(h,  VH[0][e], VL[0][e]);
                hsplit(d,  VH[1][e], VL[1][e]);
                hsplit(ev, VH[2][e], VL[2][e]);
            }
            const int ktbase = (n0 + wn * 32) >> 4;
#pragma unroll
            for (int ch = 0; ch < 3; ch++)
#pragma unroll
                for (int hl = 0; hl < 2; hl++) {
                    const __half* A = hl ? VL[ch] : VH[ch];
#pragma unroll
                    for (int p = 0; p < 2; p++) {
                        uint4 o;
                        o.x = pack2(A[4 * p],         A[4 * p + 1]);
                        o.y = pack2(A[8 + 4 * p],     A[8 + 4 * p + 1]);
                        o.z = pack2(A[4 * p + 2],     A[4 * p + 3]);
                        o.w = pack2(A[8 + 4 * p + 2], A[8 + 4 * p + 3]);
                        jout[jidx(mt16, ch, hl, ktbase + p, lane)] = o;
                    }
                }
        } else {
            float su[2] = {0.f, 0.f}, se[2] = {0.f, 0.f};
#pragma unroll
            for (int rh = 0; rh < 2; rh++)
#pragma unroll
                for (int nf = 0; nf < 4; nf++)
#pragma unroll
                    for (int u = 0; u < 2; u++) {
                        const int e = rh * 8 + nf * 2 + u;
                        const int col = n0 + wn * 32 + nf * 8 + lq * 2 + u;
                        float h = hh[e];
                        float g = fmaf(-h, h, 1.0f);
                        float ev = g * fmaf(-2.0f * h * aa[e], aa[e], cc[e]);
                        float w3 = __ldg(W3 + col);
                        su[rh] = fmaf(h, w3, su[rh]);
                        se[rh] = fmaf(ev, w3, se[rh]);
                    }
#pragma unroll
            for (int rh = 0; rh < 2; rh++) {
                float s = su[rh];
                s += __shfl_xor_sync(0xffffffffu, s, 1);
                s += __shfl_xor_sync(0xffffffffu, s, 2);
                float v = se[rh];
                v += __shfl_xor_sync(0xffffffffu, v, 1);
                v += __shfl_xor_sync(0xffffffffu, v, 2);
                if (lq == 0) {
                    const int row = mt16 * 16 + rh * 8 + lg;
                    const int p = nt * 2 + wn;
                    g_part[(size_t)row * 16 + p]     = s;
                    g_part[(size_t)row * 16 + 8 + p] = v;
                }
            }
        }
    }
}

// ---------------- tiny kernels ----------------
__global__ void k_dummy() {}

__global__ void k_head(const float* __restrict__ x, const float* __restrict__ wts,
                       const float* __restrict__ b3) {
    int i = blockIdx.x * 256 + threadIdx.x;
    const float* p = g_part + (size_t)i * 16;
    float4 a0 = *(const float4*)p,       a1 = *(const float4*)(p + 4);
    float4 a2 = *(const float4*)(p + 8), a3 = *(const float4*)(p + 12);
    float su = ((a0.x + a0.y) + (a0.z + a0.w)) + ((a1.x + a1.y) + (a1.z + a1.w));
    float se = ((a2.x + a2.y) + (a2.z + a2.w)) + ((a3.x + a3.y) + (a3.z + a3.w));
    float xi = x[i];
    g_r[i] = wts[i] * (se + my_sin(PI_F * xi));
    if (i == 0)         g_ub[0] = su + __ldg(b3);
    if (i == N_PTS - 1) g_ub[1] = su + __ldg(b3);
}

__global__ __launch_bounds__(256) void k_spec(const float* __restrict__ x) {
    const int kg  = blockIdx.x >> 3;
    const int seg = blockIdx.x & 7;
    const int k0  = kg * 8;
    const int i0  = seg * 4096;
    float pk[8];
#pragma unroll
    for (int q = 0; q < 8; q++) pk[q] = PI_F * (float)(k0 + 1 + q);
    float acc[8] = {0, 0, 0, 0, 0, 0, 0, 0};
    for (int i = threadIdx.x; i < 4096; i += 256) {
        float xi = x[i0 + i], ri = g_r[i0 + i];
#pragma unroll
        for (int q = 0; q < 8; q++)
            acc[q] = fmaf(my_sin(pk[q] * xi), ri, acc[q]);
    }
    __shared__ float sred[8][8];
    int lane = threadIdx.x & 31, wid = threadIdx.x >> 5;
#pragma unroll
    for (int q = 0; q < 8; q++) {
        float v = acc[q];
#pragma unroll
        for (int o = 16; o; o >>= 1) v += __shfl_down_sync(0xffffffffu, v, o);
        if (lane == 0) sred[q][wid] = v;
    }
    __syncthreads();
    if (threadIdx.x < 8) {
        float s = 0.f;
#pragma unroll
        for (int w = 0; w < 8; w++) s += sred[threadIdx.x][w];
        g_Sp[seg * KTEST + k0 + threadIdx.x] = s;
    }
}

__global__ void k_final(float* __restrict__ out) {
    __shared__ float sred[8];
    float s = 0.f;
    for (int t = threadIdx.x; t < KTEST; t += 256) {
        float v = 0.f;
#pragma unroll
        for (int seg = 0; seg < 8; seg++) v += g_Sp[seg * KTEST + t];
        s = fmaf(v, v, s);
    }
    int lane = threadIdx.x & 31, wid = threadIdx.x >> 5;
#pragma unroll
    for (int o = 16; o; o >>= 1) s += __shfl_down_sync(0xffffffffu, s, o);
    if (lane == 0) sred[wid] = s;
    __syncthreads();
    if (threadIdx.x == 0) {
        float t = 0.f;
#pragma unroll
        for (int w = 0; w < 8; w++) t += sred[w];
        out[0] = t * (1.0f / 1024.0f);
        out[1] = 5.0f * (g_ub[0] * g_ub[0] + g_ub[1] * g_ub[1]);
    }
}

extern "C" void kernel_launch(void* const* d_in, const int* in_sizes, int n_in,
                              void* d_out, int out_size) {
    const float* x   = (const float*)d_in[0];
    const float* wts = (const float*)d_in[1];
    const float* W0  = (const float*)d_in[2];
    const float* b0  = (const float*)d_in[3];
    const float* W1  = (const float*)d_in[4];
    const float* b1  = (const float*)d_in[5];
    const float* W2  = (const float*)d_in[6];
    const float* b2  = (const float*)d_in[7];
    const float* W3  = (const float*)d_in[8];
    const float* b3  = (const float*)d_in[9];

    void *pA = nullptr, *pB = nullptr;
    cudaGetSymbolAddress(&pA, g_jetA);
    cudaGetSymbolAddress(&pB, g_jetB);
    uint4* jA = (uint4*)pA;
    uint4* jB = (uint4*)pB;

    cudaFuncSetAttribute(k_layer<1>, cudaFuncAttributeMaxDynamicSharedMemorySize, SMEM_TOT);
    cudaFuncSetAttribute(k_layer<0>, cudaFuncAttributeMaxDynamicSharedMemorySize, SMEM_TOT);

    k_dummy   <<<1, 32>>>();   // shifts ncu -s window onto a layer kernel
    k_init    <<<4096, 256>>>(x, W0, b0, jA);
    k_layer<1><<<2048, NTHR, SMEM_TOT>>>(jA, jB, W1, b1, nullptr);
    k_layer<0><<<2048, NTHR, SMEM_TOT>>>(jB, nullptr, W2, b2, W3);
    k_head    <<<N_PTS / 256, 256>>>(x, wts, b3);
    k_spec    <<<KTEST, 256>>>(x);
    k_final   <<<1, 256>>>((float*)d_out);
}

// round 16
// speedup vs baseline: 1.0399x; 1.0399x over previous
#include <cuda_runtime.h>
#include <cuda_fp16.h>
#include <cstdint>
#include <cstddef>

#define N_PTS 32768
#define HID   256
#define KTEST 1024
#define PI_F  3.14159274101257324f

// ---------------- global scratch ----------------
// Fragment-major jets: [mt16(2048)][ch(3)][hl(2)][kt(16)][lane(32)] x uint4.
__device__ uint4 g_jetA[(size_t)2048 * 3 * 2 * 16 * 32];
__device__ uint4 g_jetB[(size_t)2048 * 3 * 2 * 16 * 32];
__device__ float g_part[(size_t)N_PTS * 16];
__device__ float g_r[N_PTS];
__device__ float g_Sp[8 * KTEST];
__device__ float g_ub[2];

// ---------------- math helpers ----------------
__device__ __forceinline__ float frcp(float x) {
    float r;
    asm("rcp.approx.f32 %0, %1;" : "=f"(r) : "f"(x));
    return r;
}

__device__ __forceinline__ void tanh4(const float* z, float* h) {
    float e[4], ep[4];
#pragma unroll
    for (int i = 0; i < 4; i++) {
        float zc = fminf(fmaxf(z[i], -9.0f), 9.0f);
        e[i]  = __expf(2.0f * zc);
        ep[i] = e[i] + 1.0f;
    }
    float p01   = ep[0] * ep[1];
    float p012  = p01 * ep[2];
    float p0123 = p012 * ep[3];
    float r = frcp(p0123);
    float i3 = p012 * r;  r *= ep[3];
    float i2 = p01  * r;  r *= ep[2];
    float i1 = ep[0] * r; r *= ep[1];
    float i0 = r;
    h[0] = (e[0] - 1.0f) * i0;
    h[1] = (e[1] - 1.0f) * i1;
    h[2] = (e[2] - 1.0f) * i2;
    h[3] = (e[3] - 1.0f) * i3;
}

__device__ __forceinline__ float my_sin(float a) {
    const float INV_PI = 0.3183098861837907f;
    float n = rintf(a * INV_PI);
    float r = fmaf(n, -3.14159274101257324f, a);
    r = fmaf(n, 8.742277657347586e-8f, r);
    float s2 = r * r;
    float p = -2.50521084e-8f;
    p = fmaf(p, s2, 2.75573192e-6f);
    p = fmaf(p, s2, -1.98412698e-4f);
    p = fmaf(p, s2, 8.33333333e-3f);
    p = fmaf(p, s2, -1.66666667e-1f);
    float s = fmaf(p * s2, r, r);
    return (((int)n) & 1) ? -s : s;
}

__device__ __forceinline__ void hsplit(float v, __half& hi, __half& lo) {
    hi = __float2half_rn(v);
    lo = __float2half_rn(v - __half2float(hi));
}

__device__ __forceinline__ uint32_t pack2(__half a, __half b) {
    __half2 t = __halves2half2(a, b);
    return *(uint32_t*)&t;
}

// fp16 HMMA (sm_80+ PTX).
__device__ __forceinline__ void mma16816(float* d, const uint32_t* a, const uint32_t* b) {
    asm volatile(
        "mma.sync.aligned.m16n8k16.row.col.f32.f16.f16.f32 "
        "{%0,%1,%2,%3}, {%4,%5,%6,%7}, {%8,%9}, {%0,%1,%2,%3};"
        : "+f"(d[0]), "+f"(d[1]), "+f"(d[2]), "+f"(d[3])
        : "r"(a[0]), "r"(a[1]), "r"(a[2]), "r"(a[3]), "r"(b[0]), "r"(b[1]));
}

// ldmatrix x4 (sm_75+ PTX).
__device__ __forceinline__ void ldsm4(uint32_t* r, uint32_t addr) {
    asm volatile("ldmatrix.sync.aligned.m8n8.x4.shared.b16 {%0,%1,%2,%3}, [%4];"
        : "=r"(r[0]), "=r"(r[1]), "=r"(r[2]), "=r"(r[3]) : "r"(addr));
}

__device__ __forceinline__ uint32_t smem_u32(const void* p) {
    uint32_t a;
    asm("{ .reg .u64 t; cvta.to.shared.u64 t, %1; cvt.u32.u64 %0, t; }" : "=r"(a) : "l"(p));
    return a;
}

// ---------------- SMEM geometry: B only (fp16 elements) ----------------
#define SB_E    136
#define BLO_E   8704                   // 64*136
#define SMEM_TOT (2 * 8704 * 2)        // 34816 B

// jet index (in uint4 units)
__device__ __forceinline__ size_t jidx(int mt16, int ch, int hl, int kt, int lane) {
    return ((((size_t)mt16 * 3 + ch) * 2 + hl) * 16 + kt) * 32 + lane;
}

// Stage one K=128 half of B = W^T (fp16 hi/lo split), n tile = 64 cols.
__device__ __forceinline__ void stage_B(__half* sm, const float* __restrict__ W,
                                        int n0, int k0, int tid) {
#pragma unroll
    for (int it = 0; it < 8; it++) {
        int e = tid + it * 256;
        int k = e >> 4, n4 = e & 15;
        float4 v = *(const float4*)(W + (size_t)(k0 + k) * HID + n0 + n4 * 4);
        float vv[4] = {v.x, v.y, v.z, v.w};
#pragma unroll
        for (int u = 0; u < 4; u++) {
            __half hh, ll; hsplit(vv[u], hh, ll);
            int off = (n4 * 4 + u) * SB_E + k;
            sm[off]         = hh;
            sm[BLO_E + off] = ll;
        }
    }
}

// ---------------- layer-0 jet init (fragment-major) ----------------
__global__ __launch_bounds__(256) void k_init(const float* __restrict__ x,
                                              const float* __restrict__ W0,
                                              const float* __restrict__ b0,
                                              uint4* __restrict__ jout) {
    int gid = blockIdx.x * 256 + threadIdx.x;
    int tile = gid >> 5, lane = gid & 31;
    int mt16 = tile >> 4, kt = tile & 15;
    int lg = lane >> 2, lq = lane & 3;

    float x0 = __ldg(x + mt16 * 16 + lg);
    float x1 = __ldg(x + mt16 * 16 + lg + 8);
    int kc[4] = {kt * 16 + 2 * lq, kt * 16 + 2 * lq + 1,
                 kt * 16 + 2 * lq + 8, kt * 16 + 2 * lq + 9};
    float w[4], b[4];
#pragma unroll
    for (int c = 0; c < 4; c++) { w[c] = __ldg(W0 + kc[c]); b[c] = __ldg(b0 + kc[c]); }

    float z[8], h[8];
#pragma unroll
    for (int c = 0; c < 4; c++) {
        z[c]     = fmaf(x0, w[c], b[c]);
        z[4 + c] = fmaf(x1, w[c], b[c]);
    }
    tanh4(z, h);
    tanh4(z + 4, h + 4);

    __half VH[3][8], VL[3][8];
#pragma unroll
    for (int e = 0; e < 8; e++) {
        int c = e & 3;
        float hv = h[e];
        float g  = fmaf(-hv, hv, 1.0f);
        float d  = g * w[c];
        float e2 = -2.0f * hv * g * w[c] * w[c];
        hsplit(hv, VH[0][e], VL[0][e]);
        hsplit(d,  VH[1][e], VL[1][e]);
        hsplit(e2, VH[2][e], VL[2][e]);
    }
#pragma unroll
    for (int ch = 0; ch < 3; ch++)
#pragma unroll
        for (int hl = 0; hl < 2; hl++) {
            const __half* A = hl ? VL[ch] : VH[ch];
            uint4 o;
            o.x = pack2(A[0], A[1]);
            o.y = pack2(A[4], A[5]);
            o.z = pack2(A[2], A[3]);
            o.w = pack2(A[6], A[7]);
            jout[jidx(mt16, ch, hl, kt, lane)] = o;
        }
}

// ---------------- fused hidden layer (R14 tiling + split-plane deep prefetch) ----------------
template<int WRITE_JET>
__global__ __launch_bounds__(256, 2) void k_layer(
    const uint4* __restrict__ jin, uint4* __restrict__ jout,
    const float* __restrict__ W, const float* __restrict__ bias,
    const float* __restrict__ W3)
{
    extern __shared__ __half sm[];
    const int tid = threadIdx.x, lane = tid & 31, wid = tid >> 5;
    const int wm = wid & 3, wn = wid >> 2;
    const int lg = lane >> 2, lq = lane & 3;
    const int t  = lane >> 3, ri = lane & 7;
    const int nt = blockIdx.x & 3, mt = blockIdx.x >> 2;
    const int n0 = nt * 64;
    const int mt16 = mt * 4 + wm;

    const uint32_t smb = smem_u32(sm);
    stage_B(sm, W, n0, 0, tid);

    float acc[3][4][4];
#pragma unroll
    for (int ch = 0; ch < 3; ch++)
#pragma unroll
        for (int nf = 0; nf < 4; nf++)
#pragma unroll
            for (int rr = 0; rr < 4; rr++) acc[ch][nf][rr] = 0.f;

    // One base pointer; all LDG offsets become compile-time immediates.
    const uint4* jbase = jin + jidx(mt16, 0, 0, 0, lane);
    // strides in uint4 units: ch: 2*16*32 = 1024; hl: 16*32 = 512; kt: 32.
#define AHI(CH, KT) __ldg(jbase + (CH) * 1024 + (KT) * 32)
#define ALO(CH, KT) __ldg(jbase + (CH) * 1024 + 512 + (KT) * 32)

    // hi-plane ring: depth 3 (distance 3); lo-plane ring: depth 2 (distance 2).
    uint4 ahi[3][3], alo[2][3];
#pragma unroll
    for (int ch = 0; ch < 3; ch++) {
        ahi[0][ch] = AHI(ch, 0);
        ahi[1][ch] = AHI(ch, 1);
        ahi[2][ch] = AHI(ch, 2);
        alo[0][ch] = ALO(ch, 0);
        alo[1][ch] = ALO(ch, 1);
    }
    __syncthreads();   // B half 0 staged

#pragma unroll
    for (int kt = 0; kt < 16; kt++) {
        if (kt == 8) {
            __syncthreads();
            stage_B(sm, W, n0, 128, tid);
            __syncthreads();
        }
        const int kb = (kt & 7) * 16;
        uint32_t bh[4][2], bl[4][2];
#pragma unroll
        for (int nf = 0; nf < 4; nf++) {
            int n = wn * 32 + nf * 8 + ri;
            uint32_t el = ((t >> 1) ? BLO_E : 0) + n * SB_E + kb + (t & 1) * 8;
            uint32_t rg[4];
            ldsm4(rg, smb + el * 2);
            bh[nf][0] = rg[0]; bh[nf][1] = rg[1];
            bl[nf][0] = rg[2]; bl[nf][1] = rg[3];
        }
        const int sh = kt % 3, sl = kt & 1;
        // pass 1 + 2 (consume ahi[sh])
#pragma unroll
        for (int ch = 0; ch < 3; ch++) {
            const uint32_t* ah = (const uint32_t*)&ahi[sh][ch];
#pragma unroll
            for (int nf = 0; nf < 4; nf++)
                mma16816(acc[ch][nf], ah, bh[nf]);   // hi*hi
#pragma unroll
            for (int nf = 0; nf < 4; nf++)
                mma16816(acc[ch][nf], ah, bl[nf]);   // hi*lo
        }
        // refill hi slot at distance 3
        if (kt + 3 < 16) {
#pragma unroll
            for (int ch = 0; ch < 3; ch++) ahi[sh][ch] = AHI(ch, kt + 3);
        }
        // pass 3 (consume alo[sl])
#pragma unroll
        for (int ch = 0; ch < 3; ch++) {
            const uint32_t* al = (const uint32_t*)&alo[sl][ch];
#pragma unroll
            for (int nf = 0; nf < 4; nf++)
                mma16816(acc[ch][nf], al, bh[nf]);   // lo*hi
        }
        // refill lo slot at distance 2
        if (kt + 2 < 16) {
#pragma unroll
            for (int ch = 0; ch < 3; ch++) alo[sl][ch] = ALO(ch, kt + 2);
        }
    }
#undef AHI
#undef ALO

    // ---- epilogue ----
    float zz[16], aa[16], cc[16], hh[16];
#pragma unroll
    for (int rh = 0; rh < 2; rh++)
#pragma unroll
        for (int nf = 0; nf < 4; nf++)
#pragma unroll
            for (int u = 0; u < 2; u++) {
                const int e = rh * 8 + nf * 2 + u;
                const int col = n0 + wn * 32 + nf * 8 + lq * 2 + u;
                zz[e] = acc[0][nf][rh * 2 + u] + __ldg(bias + col);
                aa[e] = acc[1][nf][rh * 2 + u];
                cc[e] = acc[2][nf][rh * 2 + u];
            }
    tanh4(zz, hh); tanh4(zz + 4, hh + 4);
    tanh4(zz + 8, hh + 8); tanh4(zz + 12, hh + 12);

    if (WRITE_JET) {
        __half VH[3][16], VL[3][16];
#pragma unroll
        for (int e = 0; e < 16; e++) {
            float h = hh[e];
            float g = fmaf(-h, h, 1.0f);
            float d = g * aa[e];
            float ev = g * fmaf(-2.0f * h * aa[e], aa[e], cc[e]);
            hsplit(h,  VH[0][e], VL[0][e]);
            hsplit(d,  VH[1][e], VL[1][e]);
            hsplit(ev, VH[2][e], VL[2][e]);
        }
        const int ktbase = (n0 + wn * 32) >> 4;
#pragma unroll
        for (int ch = 0; ch < 3; ch++)
#pragma unroll
            for (int hl = 0; hl < 2; hl++) {
                const __half* A = hl ? VL[ch] : VH[ch];
#pragma unroll
                for (int p = 0; p < 2; p++) {
                    uint4 o;
                    o.x = pack2(A[4 * p],         A[4 * p + 1]);
                    o.y = pack2(A[8 + 4 * p],     A[8 + 4 * p + 1]);
                    o.z = pack2(A[4 * p + 2],     A[4 * p + 3]);
                    o.w = pack2(A[8 + 4 * p + 2], A[8 + 4 * p + 3]);
                    jout[jidx(mt16, ch, hl, ktbase + p, lane)] = o;
                }
            }
    } else {
        float su[2] = {0.f, 0.f}, se[2] = {0.f, 0.f};
#pragma unroll
        for (int rh = 0; rh < 2; rh++)
#pragma unroll
            for (int nf = 0; nf < 4; nf++)
#pragma unroll
                for (int u = 0; u < 2; u++) {
                    const int e = rh * 8 + nf * 2 + u;
                    const int col = n0 + wn * 32 + nf * 8 + lq * 2 + u;
                    float h = hh[e];
                    float g = fmaf(-h, h, 1.0f);
                    float ev = g * fmaf(-2.0f * h * aa[e], aa[e], cc[e]);
                    float w3 = __ldg(W3 + col);
                    su[rh] = fmaf(h, w3, su[rh]);
                    se[rh] = fmaf(ev, w3, se[rh]);
                }
#pragma unroll
        for (int rh = 0; rh < 2; rh++) {
            float s = su[rh];
            s += __shfl_xor_sync(0xffffffffu, s, 1);
            s += __shfl_xor_sync(0xffffffffu, s, 2);
            float v = se[rh];
            v += __shfl_xor_sync(0xffffffffu, v, 1);
            v += __shfl_xor_sync(0xffffffffu, v, 2);
            if (lq == 0) {
                const int row = mt16 * 16 + rh * 8 + lg;
                const int p = nt * 2 + wn;
                g_part[(size_t)row * 16 + p]     = s;
                g_part[(size_t)row * 16 + 8 + p] = v;
            }
        }
    }
}

// ---------------- tiny kernels ----------------
__global__ void k_dummy() {}

__global__ void k_head(const float* __restrict__ x, const float* __restrict__ wts,
                       const float* __restrict__ b3) {
    int i = blockIdx.x * 256 + threadIdx.x;
    const float* p = g_part + (size_t)i * 16;
    float4 a0 = *(const float4*)p,       a1 = *(const float4*)(p + 4);
    float4 a2 = *(const float4*)(p + 8), a3 = *(const float4*)(p + 12);
    float su = ((a0.x + a0.y) + (a0.z + a0.w)) + ((a1.x + a1.y) + (a1.z + a1.w));
    float se = ((a2.x + a2.y) + (a2.z + a2.w)) + ((a3.x + a3.y) + (a3.z + a3.w));
    float xi = x[i];
    g_r[i] = wts[i] * (se + my_sin(PI_F * xi));
    if (i == 0)         g_ub[0] = su + __ldg(b3);
    if (i == N_PTS - 1) g_ub[1] = su + __ldg(b3);
}

__global__ __launch_bounds__(256) void k_spec(const float* __restrict__ x) {
    const int kg  = blockIdx.x >> 3;
    const int seg = blockIdx.x & 7;
    const int k0  = kg * 8;
    const int i0  = seg * 4096;
    float pk[8];
#pragma unroll
    for (int q = 0; q < 8; q++) pk[q] = PI_F * (float)(k0 + 1 + q);
    float acc[8] = {0, 0, 0, 0, 0, 0, 0, 0};
    for (int i = threadIdx.x; i < 4096; i += 256) {
        float xi = x[i0 + i], ri = g_r[i0 + i];
#pragma unroll
        for (int q = 0; q < 8; q++)
            acc[q] = fmaf(my_sin(pk[q] * xi), ri, acc[q]);
    }
    __shared__ float sred[8][8];
    int lane = threadIdx.x & 31, wid = threadIdx.x >> 5;
#pragma unroll
    for (int q = 0; q < 8; q++) {
        float v = acc[q];
#pragma unroll
        for (int o = 16; o; o >>= 1) v += __shfl_down_sync(0xffffffffu, v, o);
        if (lane == 0) sred[q][wid] = v;
    }
    __syncthreads();
    if (threadIdx.x < 8) {
        float s = 0.f;
#pragma unroll
        for (int w = 0; w < 8; w++) s += sred[threadIdx.x][w];
        g_Sp[seg * KTEST + k0 + threadIdx.x] = s;
    }
}

__global__ void k_final(float* __restrict__ out) {
    __shared__ float sred[8];
    float s = 0.f;
    for (int t = threadIdx.x; t < KTEST; t += 256) {
        float v = 0.f;
#pragma unroll
        for (int seg = 0; seg < 8; seg++) v += g_Sp[seg * KTEST + t];
        s = fmaf(v, v, s);
    }
    int lane = threadIdx.x & 31, wid = threadIdx.x >> 5;
#pragma unroll
    for (int o = 16; o; o >>= 1) s += __shfl_down_sync(0xffffffffu, s, o);
    if (lane == 0) sred[wid] = s;
    __syncthreads();
    if (threadIdx.x == 0) {
        float t = 0.f;
#pragma unroll
        for (int w = 0; w < 8; w++) t += sred[w];
        out[0] = t * (1.0f / 1024.0f);
        out[1] = 5.0f * (g_ub[0] * g_ub[0] + g_ub[1] * g_ub[1]);
    }
}

extern "C" void kernel_launch(void* const* d_in, const int* in_sizes, int n_in,
                              void* d_out, int out_size) {
    const float* x   = (const float*)d_in[0];
    const float* wts = (const float*)d_in[1];
    const float* W0  = (const float*)d_in[2];
    const float* b0  = (const float*)d_in[3];
    const float* W1  = (const float*)d_in[4];
    const float* b1  = (const float*)d_in[5];
    const float* W2  = (const float*)d_in[6];
    const float* b2  = (const float*)d_in[7];
    const float* W3  = (const float*)d_in[8];
    const float* b3  = (const float*)d_in[9];

    void *pA = nullptr, *pB = nullptr;
    cudaGetSymbolAddress(&pA, g_jetA);
    cudaGetSymbolAddress(&pB, g_jetB);
    uint4* jA = (uint4*)pA;
    uint4* jB = (uint4*)pB;

    cudaFuncSetAttribute(k_layer<1>, cudaFuncAttributeMaxDynamicSharedMemorySize, SMEM_TOT);
    cudaFuncSetAttribute(k_layer<0>, cudaFuncAttributeMaxDynamicSharedMemorySize, SMEM_TOT);

    k_dummy   <<<1, 32>>>();   // shifts ncu -s window onto a layer kernel
    k_init    <<<4096, 256>>>(x, W0, b0, jA);
    k_layer<1><<<2048, 256, SMEM_TOT>>>(jA, jB, W1, b1, nullptr);
    k_layer<0><<<2048, 256, SMEM_TOT>>>(jB, nullptr, W2, b2, W3);
    k_head    <<<N_PTS / 256, 256>>>(x, wts, b3);
    k_spec    <<<KTEST, 256>>>(x);
    k_final   <<<1, 256>>>((float*)d_out);
}